// round 1
// baseline (speedup 1.0000x reference)
#include <cuda_runtime.h>

// YOLOV3TargetMerger — HBM-bound masked merge + small IOU reduction.
// Shapes fixed by the problem instance:
//   b=32, N=22743, M=50, C=80
// Outputs concatenated flat in reference tuple order:
//   objectness    [b,N,1]  at out + 0
//   center_targets[b,N,2]  at out + 1*BN
//   scale_targets [b,N,2]  at out + 3*BN
//   weights       [b,N,2]  at out + 5*BN
//   class_targets [b,N,C]  at out + 7*BN
//   class_mask    [b,N,C]  at out + (7+C)*BN

#define BB   32
#define NN   22743
#define MM   50
#define CC   80
#define BN   ((long long)BB * NN)          // 727776
#define VEC_PER_ANCHOR (CC / 4)            // 20
#define IGNORE_IOU 0.7f
#define EPS_IOU 1e-12f

// ---------------------------------------------------------------------------
// Kernel A: per-anchor small fields. grid = (ceil(N/256), b), block = 256.
// ---------------------------------------------------------------------------
__global__ __launch_bounds__(256)
void yolo_small_fields_kernel(const float* __restrict__ box_preds,   // [b,N,4]
                              const float* __restrict__ gt_boxes,    // [b,M,4]
                              const float* __restrict__ obj_t,       // [b,N,1]
                              const float* __restrict__ centers_t,   // [b,N,2]
                              const float* __restrict__ scales_t,    // [b,N,2]
                              const float* __restrict__ weights_t,   // [b,N,2]
                              float* __restrict__ out)
{
    __shared__ float4 s_gt[MM];
    __shared__ float  s_area[MM];

    const int b   = blockIdx.y;
    const int tid = threadIdx.x;

    // Stage this batch's GT boxes + areas into SMEM (50 * 16B = 800B).
    if (tid < MM) {
        float4 g = reinterpret_cast<const float4*>(gt_boxes)[(long long)b * MM + tid];
        s_gt[tid]   = g;
        s_area[tid] = (g.z - g.x) * (g.w - g.y);
    }
    __syncthreads();

    const int n = blockIdx.x * blockDim.x + tid;
    if (n >= NN) return;
    const long long a = (long long)b * NN + n;

    const float obj  = obj_t[a];
    const bool  mask = obj > 0.0f;

    float objout;
    if (mask) {
        objout = obj;                 // dyn target is dead code -> skip IOU entirely
    } else {
        const float4 p  = reinterpret_cast<const float4*>(box_preds)[a];
        const float  ap = (p.z - p.x) * (p.w - p.y);
        float mx = 0.0f;
        #pragma unroll
        for (int m = 0; m < MM; ++m) {
            const float4 g = s_gt[m];
            const float tlx = fmaxf(p.x, g.x);
            const float tly = fmaxf(p.y, g.y);
            const float brx = fminf(p.z, g.z);
            const float bry = fminf(p.w, g.w);
            const float w = fmaxf(brx - tlx, 0.0f);
            const float h = fmaxf(bry - tly, 0.0f);
            const float inter = w * h;
            const float uni   = ap + s_area[m] - inter;
            const float iou   = inter / (uni + EPS_IOU);
            mx = fmaxf(mx, iou);
        }
        objout = (mx > IGNORE_IOU) ? -1.0f : 0.0f;
    }

    out[a] = objout;

    float2 c, s, w;
    if (mask) {
        c = reinterpret_cast<const float2*>(centers_t)[a];
        s = reinterpret_cast<const float2*>(scales_t)[a];
        w = reinterpret_cast<const float2*>(weights_t)[a];
    } else {
        c = make_float2(0.0f, 0.0f);
        s = make_float2(0.0f, 0.0f);
        w = make_float2(0.0f, 0.0f);
    }
    reinterpret_cast<float2*>(out + 1 * BN)[a] = c;
    reinterpret_cast<float2*>(out + 3 * BN)[a] = s;
    reinterpret_cast<float2*>(out + 5 * BN)[a] = w;
}

// ---------------------------------------------------------------------------
// Kernel B: class_targets + class_mask, one thread per float4 group of C.
// total threads = BN * 20. When !mask, clas_t is NOT read (explicit branch).
// ---------------------------------------------------------------------------
__global__ __launch_bounds__(256)
void yolo_class_fields_kernel(const float*  __restrict__ obj_t,   // [b,N,1]
                              const float4* __restrict__ clas,    // [b,N,C] as float4
                              float4* __restrict__ class_t,       // out + 7*BN
                              float4* __restrict__ class_m)       // out + (7+C)*BN
{
    const long long total = BN * VEC_PER_ANCHOR;
    const long long i = (long long)blockIdx.x * blockDim.x + threadIdx.x;
    if (i >= total) return;

    const long long anchor = i / VEC_PER_ANCHOR;     // 20-way L1 broadcast read
    const bool mask = __ldg(obj_t + anchor) > 0.0f;

    float4 t, m;
    if (mask) {
        const float4 v = clas[i];
        t = v;
        m = make_float4(v.x >= 0.0f ? 1.0f : 0.0f,
                        v.y >= 0.0f ? 1.0f : 0.0f,
                        v.z >= 0.0f ? 1.0f : 0.0f,
                        v.w >= 0.0f ? 1.0f : 0.0f);
    } else {
        t = make_float4(-1.0f, -1.0f, -1.0f, -1.0f);
        m = make_float4(0.0f, 0.0f, 0.0f, 0.0f);
    }
    class_t[i] = t;
    class_m[i] = m;
}

// ---------------------------------------------------------------------------
extern "C" void kernel_launch(void* const* d_in, const int* in_sizes, int n_in,
                              void* d_out, int out_size)
{
    const float* box_preds = (const float*)d_in[0];
    const float* gt_boxes  = (const float*)d_in[1];
    const float* obj_t     = (const float*)d_in[2];
    const float* centers_t = (const float*)d_in[3];
    const float* scales_t  = (const float*)d_in[4];
    const float* weights_t = (const float*)d_in[5];
    const float* clas_t    = (const float*)d_in[6];
    float* out = (float*)d_out;

    // Kernel A: small fields + IOU
    {
        dim3 grid((NN + 255) / 256, BB);
        yolo_small_fields_kernel<<<grid, 256>>>(box_preds, gt_boxes, obj_t,
                                                centers_t, scales_t, weights_t, out);
    }

    // Kernel B: class fields
    {
        const long long total = BN * VEC_PER_ANCHOR;        // 14,555,520
        const int blocks = (int)((total + 255) / 256);
        yolo_class_fields_kernel<<<blocks, 256>>>(obj_t,
                                                  (const float4*)clas_t,
                                                  (float4*)(out + 7 * BN),
                                                  (float4*)(out + (7 + CC) * BN));
    }
}